// round 15
// baseline (speedup 1.0000x reference)
#include <cuda_runtime.h>
#include <cuda_fp16.h>
#include <math.h>
#include <stdint.h>

#define B_    32
#define CIN   3
#define HIN   224
#define WIN   224
#define CO    192
#define OH    112
#define OW    112
#define PH    56
#define PW    56
#define NPC   (B_*OH*OW)   // 401408

// padded y layout: per (b,c) plane = 113 rows x 128 halves.
// row 0 = NaN halo; y row r at row r+1; y col c at col c+4.
#define PP     128
#define PROWS  113

// -------- device scratch ----------------------------------------------------
__device__ __half g_yh[(size_t)B_*CO*PROWS*PP];   // ~178 MB padded conv output
__device__ float g_sum[CO];                       // zeroed at load; finalize re-zeroes
__device__ float g_sq[CO];
__device__ float g_scale[CO];
__device__ float g_shift[CO];

// ---------------------------------------------------------------------------
__device__ __forceinline__ void mma16816(float& d0, float& d1, float& d2, float& d3,
                                         uint32_t a0, uint32_t a1, uint32_t a2, uint32_t a3,
                                         uint32_t b0, uint32_t b1) {
    asm volatile(
        "mma.sync.aligned.m16n8k16.row.col.f32.f16.f16.f32 "
        "{%0,%1,%2,%3},{%4,%5,%6,%7},{%8,%9},{%0,%1,%2,%3};"
        : "+f"(d0), "+f"(d1), "+f"(d2), "+f"(d3)
        : "r"(a0), "r"(a1), "r"(a2), "r"(a3), "r"(b0), "r"(b1));
}

__device__ __forceinline__ void ldsm_x4(uint32_t& r0, uint32_t& r1,
                                        uint32_t& r2, uint32_t& r3, uint32_t p) {
    asm volatile("ldmatrix.sync.aligned.m8n8.x4.shared.b16 {%0,%1,%2,%3},[%4];"
                 : "=r"(r0), "=r"(r1), "=r"(r2), "=r"(r3) : "r"(p));
}

__device__ __forceinline__ void bulk_copy_s2g(void* gdst, uint32_t ssrc, int bytes) {
    asm volatile("cp.async.bulk.global.shared::cta.bulk_group [%0], [%1], %2;"
                 :: "l"(gdst), "r"(ssrc), "r"(bytes) : "memory");
}

// ---------------------------------------------------------------------------
// Implicit-GEMM conv, 2 output rows per block.  (hot loop FROZEN from R12;
// A built directly from fp32 conv_w — no wprep launch)
#define CONV_THREADS 448
#define RPB     2
#define XROWS   5
#define XPITCH  232
#define APITCH  40
#define BPITCH  40
#define SYP     136                          // staging pitch (halves)
#define A_OFF   0                            // 192*40  = 7680
#define X_OFF   (CO*APITCH)                  // 15*232  = 3480
#define B_OFF   (X_OFF + CIN*XROWS*XPITCH)   // 112*40  = 4480
#define Y_OFF   (B_OFF + OW*BPITCH)          // 192*136 = 26112
#define H_TOT   (Y_OFF + CO*SYP)             // 41752 halves
#define NF      (192 + 2*CO*7)               // bias + sum/sq slots = 2880 floats
#define CONV_SMEM (H_TOT*2 + NF*4)           // 95024 B

__global__ __launch_bounds__(CONV_THREADS, 2)
void conv_mma_kernel(const float* __restrict__ x,
                     const float* __restrict__ conv_w,
                     const float* __restrict__ conv_b) {
    extern __shared__ __half sm[];
    __half* A_s = sm + A_OFF;
    __half* sX  = sm + X_OFF;
    __half* B_s = sm + B_OFF;
    __half* sY  = sm + Y_OFF;
    float*  sBias = (float*)(sm + H_TOT);
    float*  sSumP = sBias + 192;         // [192][7]
    float*  sSqP  = sSumP + CO*7;        // [192][7]

    const int tid  = threadIdx.x;
    const int lane = tid & 31;
    const int w    = tid >> 5;
    const int rt   = blockIdx.x;    // 2-row tile, 0..55
    const int b    = blockIdx.y;

    if (tid < 192) sBias[tid] = conv_b[tid];
    for (int i = tid; i < CO*7; i += CONV_THREADS) { sSumP[i] = 0.f; sSqP[i] = 0.f; }

    // ---- A: build fp16 weights directly from fp32 conv_w (k 27..31 = 0) ----
    for (int i = tid; i < CO*32; i += CONV_THREADS) {
        int co = i >> 5, k = i & 31;
        float v = (k < 27) ? conv_w[co*27 + k] : 0.f;
        A_s[co*APITCH + k] = __float2half(v);
    }

    // ---- stage 5 rows x 3 ci, coalesced: warp -> (ci,row) pair ----
    for (int pair = w; pair < CIN*XROWS; pair += 14) {
        int ci = pair / XROWS;
        int r  = pair - ci*XROWS;
        int gr = 4*rt - 1 + r;
        __half* row = &sX[pair*XPITCH];
        if (gr < 0 || gr >= HIN) {
            if (lane < 29) *(uint4*)&row[8*lane] = make_uint4(0,0,0,0);
        } else {
            const float4* xb = (const float4*)(x + ((size_t)(b*CIN + ci)*HIN + gr)*WIN);
            float4 a = xb[lane];
            *(__half2*)&row[2 + 4*lane]     = __floats2half2_rn(a.x, a.y);
            *(__half2*)&row[2 + 4*lane + 2] = __floats2half2_rn(a.z, a.w);
            if (lane < 24) {
                float4 c4 = xb[lane + 32];
                *(__half2*)&row[2 + 4*(lane+32)]     = __floats2half2_rn(c4.x, c4.y);
                *(__half2*)&row[2 + 4*(lane+32) + 2] = __floats2half2_rn(c4.z, c4.w);
            } else if (lane == 24) {
                *(__half2*)&row[0] = __floats2half2_rn(0.f, 0.f);
            }
        }
    }

    // ---- staging NaN halo cols (once) ----
    {
        const __half2 NH2 = __halves2half2(__ushort_as_half((unsigned short)0x7e00),
                                           __ushort_as_half((unsigned short)0x7e00));
        for (int i = tid; i < CO*8; i += CONV_THREADS) {
            int ch = i >> 3, j = i & 7;
            int col = (j < 2) ? 2*j : 116 + 2*(j - 2);
            *(__half2*)&sY[ch*SYP + col] = NH2;
        }
    }

    // ---- top halo row 0 in gmem (rt==0 blocks only) ----
    if (rt == 0) {
        uint4 nv;
        nv.x = nv.y = nv.z = nv.w = 0x7e007e00u;
        for (int i = tid; i < CO*16; i += CONV_THREADS) {
            int ch = i >> 4, cu = i & 15;
            *(uint4*)(g_yh + ((size_t)(b*CO + ch)*PROWS)*PP + cu*8) = nv;
        }
    }
    __syncthreads();

    const int mh = w & 1;
    const int ng = w >> 1;
    const int qr = lane >> 2;
    const int qc = lane & 3;

    const uint32_t a_base = (uint32_t)__cvta_generic_to_shared(A_s)
                          + (uint32_t)((lane & 15) * (APITCH*2))
                          + (uint32_t)((lane & 16) ? 16 : 0)
                          + (uint32_t)(mh ? 6*16*APITCH*2 : 0);

    const uint32_t sy_row = (tid < 192)
        ? (uint32_t)__cvta_generic_to_shared(&sY[tid*SYP]) : 0u;

    #pragma unroll 1
    for (int oyl = 0; oyl < RPB; ++oyl) {
        // ---- build B [112 n][40 k] ----
        {
            int ci = lane / 9;
            int rr = lane - ci*9;
            int ky = rr / 3;
            int kx = rr - ky*3;
            const __half* xs = &sX[(ci*XROWS + 2*oyl + ky)*XPITCH + kx + 1];
            #pragma unroll
            for (int j = 0; j < 8; ++j) {
                int n = w + 14*j;
                __half v = __float2half(0.f);
                if (lane < 27) v = xs[2*n];
                B_s[n*BPITCH + lane] = v;
            }
        }
        if (tid < 192)
            asm volatile("cp.async.bulk.wait_group 0;" ::: "memory");
        __syncthreads();

        // ---- MMA ----
        float acc[6][2][4];
        #pragma unroll
        for (int mi = 0; mi < 6; ++mi)
            #pragma unroll
            for (int ni = 0; ni < 2; ++ni)
                #pragma unroll
                for (int j = 0; j < 4; ++j) acc[mi][ni][j] = 0.f;

        #pragma unroll
        for (int ks = 0; ks < 2; ++ks) {
            const int kb = ks*16 + 2*qc;
            uint32_t bf[2][2];
            #pragma unroll
            for (int ni = 0; ni < 2; ++ni) {
                const __half* bp = &B_s[(ng*16 + ni*8 + qr)*BPITCH + kb];
                bf[ni][0] = *(const uint32_t*)(bp);
                bf[ni][1] = *(const uint32_t*)(bp + 8);
            }
            #pragma unroll
            for (int mi = 0; mi < 6; ++mi) {
                uint32_t a0, a1, a2, a3;
                ldsm_x4(a0, a1, a2, a3,
                        a_base + (uint32_t)(mi*16*APITCH*2 + ks*32));
                #pragma unroll
                for (int ni = 0; ni < 2; ++ni)
                    mma16816(acc[mi][ni][0], acc[mi][ni][1], acc[mi][ni][2], acc[mi][ni][3],
                             a0, a1, a2, a3, bf[ni][0], bf[ni][1]);
            }
        }

        // ---- bias, stats (smem slots), staging STS ----
        #pragma unroll
        for (int mi = 0; mi < 6; ++mi) {
            const int R0 = (mh*6 + mi)*16 + qr;
            const int R8 = R0 + 8;
            const float bias0 = sBias[R0];
            const float bias8 = sBias[R8];
            float s0 = 0.f, q0 = 0.f, s8 = 0.f, q8 = 0.f;
            #pragma unroll
            for (int ni = 0; ni < 2; ++ni) {
                const int C = ng*16 + ni*8 + 2*qc;
                float v0 = acc[mi][ni][0] + bias0;
                float v1 = acc[mi][ni][1] + bias0;
                float v2 = acc[mi][ni][2] + bias8;
                float v3 = acc[mi][ni][3] + bias8;
                *(__half2*)&sY[R0*SYP + 4 + C] = __floats2half2_rn(v0, v1);
                *(__half2*)&sY[R8*SYP + 4 + C] = __floats2half2_rn(v2, v3);
                s0 += v0 + v1;  q0 += v0*v0 + v1*v1;
                s8 += v2 + v3;  q8 += v2*v2 + v3*v3;
            }
            #pragma unroll
            for (int o = 1; o <= 2; o <<= 1) {
                s0 += __shfl_xor_sync(0xffffffffu, s0, o);
                q0 += __shfl_xor_sync(0xffffffffu, q0, o);
                s8 += __shfl_xor_sync(0xffffffffu, s8, o);
                q8 += __shfl_xor_sync(0xffffffffu, q8, o);
            }
            if (qc == 0) {
                sSumP[R0*7 + ng] += s0;
                sSqP [R0*7 + ng] += q0;
                sSumP[R8*7 + ng] += s8;
                sSqP [R8*7 + ng] += q8;
            }
        }
        __syncthreads();

        // ---- DMA copy-out ----
        if (tid < 192) {
            const int OY = 2*rt + oyl;
            asm volatile("fence.proxy.async.shared::cta;" ::: "memory");
            bulk_copy_s2g(g_yh + ((size_t)(b*CO + tid)*PROWS + OY + 1)*PP,
                          sy_row, 256);
            asm volatile("cp.async.bulk.commit_group;" ::: "memory");
        }
    }

    // ---- block-level stats reduce, then drain bulk copies ----
    if (tid < 192) {
        float s = 0.f, q = 0.f;
        #pragma unroll
        for (int j = 0; j < 7; ++j) { s += sSumP[tid*7 + j]; q += sSqP[tid*7 + j]; }
        atomicAdd(&g_sum[tid], s);
        atomicAdd(&g_sq [tid], q);
        asm volatile("cp.async.bulk.wait_group 0;" ::: "memory");
    }
}

// ---------------------------------------------------------------------------
// Computes per-channel scale/shift once, re-zeroes accumulators for the next
// graph replay (no separate zero kernel needed).
__global__ void finalize_stats_kernel(const float* __restrict__ gamma,
                                      const float* __restrict__ beta) {
    int c = threadIdx.x;
    if (c >= CO) return;
    float invN  = 1.0f / (float)NPC;
    float mean  = g_sum[c] * invN;
    float var   = g_sq[c] * invN - mean*mean;
    float inv   = rsqrtf(var + 1e-5f);
    float scale = gamma[c] * inv;
    g_scale[c]  = scale;
    g_shift[c]  = beta[c] - mean*scale;
    g_sum[c] = 0.f;
    g_sq [c] = 0.f;
}

// ---------------------------------------------------------------------------
// BN + GELU + MaxPool (R13 measured-best body), direct from padded gmem.
// Thread -> 8 output cols x 2 output rows (16 outputs).
#define POOL_THREADS 256
#define POOL_TOTAL  (B_*CO*(PH/2)*(PW/8))   // 1,204,224

__device__ __forceinline__ float gelu_win(__half wm, __half wM,
                                          float scale, float shift) {
    float a1 = fmaf(__half2float(wm), scale, shift);
    float a2 = fmaf(__half2float(wM), scale, shift);
    float lo = fminf(a1, a2);
    float hi = fmaxf(a1, a2);
    float r  = 0.5f*hi*(1.0f + erff(hi*0.70710678118654752f));
    if (hi < 0.f) {
        float gl = 0.5f*lo*(1.0f + erff(lo*0.70710678118654752f));
        r = fmaxf(r, gl);
    }
    return r;
}

__global__ __launch_bounds__(POOL_THREADS)
void bn_gelu_pool_kernel(float* __restrict__ out) {
    const int idx = blockIdx.x*POOL_THREADS + threadIdx.x;
    const int g   = idx % 7;             // col group: px = 8g
    const int t1  = idx / 7;
    const int u   = t1 % 28;             // row pair: py0 = 2u
    const int t2  = t1 / 28;             // b*CO + ch
    const int ch  = t2 % CO;
    const int px  = 8*g;
    const int py0 = 2*u;

    const float scale = g_scale[ch];
    const float shift = g_shift[ch];

    const __half* base = g_yh + (size_t)t2*(PROWS*PP) + (size_t)(4*u)*PP + 2*px;

    union U { uint4 v[3]; __half2 h[12]; };
    U r0, r1, r2;
    #pragma unroll
    for (int k = 0; k < 3; ++k) r0.v[k] = *(const uint4*)(base + 8*k);
    #pragma unroll
    for (int k = 0; k < 3; ++k) r1.v[k] = *(const uint4*)(base + PP + 8*k);
    #pragma unroll
    for (int k = 0; k < 3; ++k) r2.v[k] = *(const uint4*)(base + 2*PP + 8*k);

    __half2 vmin[12], vmax[12];
    #pragma unroll
    for (int j = 0; j < 12; ++j) {
        vmax[j] = __hmax2(__hmax2(r0.h[j], r1.h[j]), r2.h[j]);
        vmin[j] = __hmin2(__hmin2(r0.h[j], r1.h[j]), r2.h[j]);
    }

    float* op0 = &out[(size_t)(t2*PH + py0)*PW + px];

    {   // outputs for py0
        const __half* Hm = (const __half*)vmin;
        const __half* HM = (const __half*)vmax;
        float4 oA, oB;
        float* ovA = (float*)&oA;
        float* ovB = (float*)&oB;
        #pragma unroll
        for (int j = 0; j < 4; ++j) {
            ovA[j] = gelu_win(__hmin(Hm[2*j+3], __hmin(Hm[2*j+4], Hm[2*j+5])),
                              __hmax(HM[2*j+3], __hmax(HM[2*j+4], HM[2*j+5])),
                              scale, shift);
            ovB[j] = gelu_win(__hmin(Hm[2*j+11], __hmin(Hm[2*j+12], Hm[2*j+13])),
                              __hmax(HM[2*j+11], __hmax(HM[2*j+12], HM[2*j+13])),
                              scale, shift);
        }
        *(float4*)op0       = oA;
        *(float4*)(op0 + 4) = oB;
    }

    U r3, r4;
    #pragma unroll
    for (int k = 0; k < 3; ++k) r3.v[k] = *(const uint4*)(base + 3*PP + 8*k);
    #pragma unroll
    for (int k = 0; k < 3; ++k) r4.v[k] = *(const uint4*)(base + 4*PP + 8*k);

    #pragma unroll
    for (int j = 0; j < 12; ++j) {
        vmax[j] = __hmax2(__hmax2(r2.h[j], r3.h[j]), r4.h[j]);
        vmin[j] = __hmin2(__hmin2(r2.h[j], r3.h[j]), r4.h[j]);
    }

    {   // outputs for py0+1
        const __half* Hm = (const __half*)vmin;
        const __half* HM = (const __half*)vmax;
        float4 oA, oB;
        float* ovA = (float*)&oA;
        float* ovB = (float*)&oB;
        #pragma unroll
        for (int j = 0; j < 4; ++j) {
            ovA[j] = gelu_win(__hmin(Hm[2*j+3], __hmin(Hm[2*j+4], Hm[2*j+5])),
                              __hmax(HM[2*j+3], __hmax(HM[2*j+4], HM[2*j+5])),
                              scale, shift);
            ovB[j] = gelu_win(__hmin(Hm[2*j+11], __hmin(Hm[2*j+12], Hm[2*j+13])),
                              __hmax(HM[2*j+11], __hmax(HM[2*j+12], HM[2*j+13])),
                              scale, shift);
        }
        *(float4*)(op0 + PW)     = oA;
        *(float4*)(op0 + PW + 4) = oB;
    }
}

// ---------------------------------------------------------------------------
extern "C" void kernel_launch(void* const* d_in, const int* in_sizes, int n_in,
                              void* d_out, int out_size) {
    const float* x      = (const float*)d_in[0];
    const float* conv_w = (const float*)d_in[1];
    const float* conv_b = (const float*)d_in[2];
    const float* gamma  = (const float*)d_in[3];
    const float* beta   = (const float*)d_in[4];
    float* out = (float*)d_out;

    cudaFuncSetAttribute(conv_mma_kernel,
                         cudaFuncAttributeMaxDynamicSharedMemorySize, CONV_SMEM);

    conv_mma_kernel<<<dim3(56, B_), CONV_THREADS, CONV_SMEM>>>(x, conv_w, conv_b);
    finalize_stats_kernel<<<1, CO>>>(gamma, beta);
    bn_gelu_pool_kernel<<<POOL_TOTAL/POOL_THREADS, POOL_THREADS>>>(out);
}

// round 16
// speedup vs baseline: 1.0905x; 1.0905x over previous
#include <cuda_runtime.h>
#include <cuda_fp16.h>
#include <math.h>
#include <stdint.h>

#define B_    32
#define CIN   3
#define HIN   224
#define WIN   224
#define CO    192
#define OH    112
#define OW    112
#define PH    56
#define PW    56
#define NPC   (B_*OH*OW)   // 401408

// padded y layout: per (b,c) plane = 113 rows x 128 halves.
// row 0 = NaN halo; y row r at row r+1; y col c at col c+4.
#define PP     128
#define PROWS  113

// -------- device scratch ----------------------------------------------------
__device__ __half g_yh[(size_t)B_*CO*PROWS*PP];   // ~178 MB padded conv output
__device__ __half g_wh[CO*32];                    // fp16 weights, taps 27..31 = 0
__device__ float g_sum[CO];                       // zeroed at load; finalize re-zeroes
__device__ float g_sq[CO];
__device__ float g_scale[CO];
__device__ float g_shift[CO];

// ---------------------------------------------------------------------------
__global__ void wprep_kernel(const float* __restrict__ conv_w) {
    int i = blockIdx.x*256 + threadIdx.x;
    if (i >= CO*32) return;
    int co = i >> 5, k = i & 31;
    float v = (k < 27) ? conv_w[co*27 + k] : 0.f;
    g_wh[i] = __float2half(v);
}

// ---------------------------------------------------------------------------
__device__ __forceinline__ void mma16816(float& d0, float& d1, float& d2, float& d3,
                                         uint32_t a0, uint32_t a1, uint32_t a2, uint32_t a3,
                                         uint32_t b0, uint32_t b1) {
    asm volatile(
        "mma.sync.aligned.m16n8k16.row.col.f32.f16.f16.f32 "
        "{%0,%1,%2,%3},{%4,%5,%6,%7},{%8,%9},{%0,%1,%2,%3};"
        : "+f"(d0), "+f"(d1), "+f"(d2), "+f"(d3)
        : "r"(a0), "r"(a1), "r"(a2), "r"(a3), "r"(b0), "r"(b1));
}

__device__ __forceinline__ void ldsm_x4(uint32_t& r0, uint32_t& r1,
                                        uint32_t& r2, uint32_t& r3, uint32_t p) {
    asm volatile("ldmatrix.sync.aligned.m8n8.x4.shared.b16 {%0,%1,%2,%3},[%4];"
                 : "=r"(r0), "=r"(r1), "=r"(r2), "=r"(r3) : "r"(p));
}

__device__ __forceinline__ void bulk_copy_s2g(void* gdst, uint32_t ssrc, int bytes) {
    asm volatile("cp.async.bulk.global.shared::cta.bulk_group [%0], [%1], %2;"
                 :: "l"(gdst), "r"(ssrc), "r"(bytes) : "memory");
}

// ---------------------------------------------------------------------------
// Implicit-GEMM conv, 4 output rows per block (S amortized; hot loop = R12).
// 448 thr = 14 warps. Warp w: mh=w&1 -> 96 channels, ng=w>>1 -> 16 cols.
#define CONV_THREADS 448
#define RPB     4
#define XROWS   9
#define XPITCH  232
#define APITCH  40
#define BPITCH  40
#define SYP     136                          // staging pitch (halves)
#define A_OFF   0                            // 192*40  = 7680
#define X_OFF   (CO*APITCH)                  // 27*232  = 6264
#define B_OFF   (X_OFF + CIN*XROWS*XPITCH)   // 112*40  = 4480
#define Y_OFF   (B_OFF + OW*BPITCH)          // 192*136 = 26112
#define H_TOT   (Y_OFF + CO*SYP)             // 44536 halves
#define NF      (192 + 2*CO*7)               // bias + sum/sq slots = 2880 floats
#define CONV_SMEM (H_TOT*2 + NF*4)           // 89072 + 11520 = 100592 B

__global__ __launch_bounds__(CONV_THREADS, 2)
void conv_mma_kernel(const float* __restrict__ x,
                     const float* __restrict__ conv_b) {
    extern __shared__ __half sm[];
    __half* A_s = sm + A_OFF;
    __half* sX  = sm + X_OFF;
    __half* B_s = sm + B_OFF;
    __half* sY  = sm + Y_OFF;
    float*  sBias = (float*)(sm + H_TOT);
    float*  sSumP = sBias + 192;         // [192][7]
    float*  sSqP  = sSumP + CO*7;        // [192][7]

    const int tid  = threadIdx.x;
    const int lane = tid & 31;
    const int w    = tid >> 5;
    const int rt   = blockIdx.x;    // 4-row tile, 0..27
    const int b    = blockIdx.y;

    if (tid < 192) sBias[tid] = conv_b[tid];
    for (int i = tid; i < CO*7; i += CONV_THREADS) { sSumP[i] = 0.f; sSqP[i] = 0.f; }

    // ---- A: copy prebuilt fp16 weights (proven fast path) ----
    {
        const uint32_t* src = (const uint32_t*)g_wh;
        uint32_t* dst = (uint32_t*)A_s;          // pitch 20 uints
        for (int i = tid; i < CO*16; i += CONV_THREADS) {
            int co = i >> 4, ku = i & 15;
            dst[co*20 + ku] = src[i];
        }
    }

    // ---- stage 9 rows x 3 ci, coalesced: warp -> (ci,row) pair ----
    for (int pair = w; pair < CIN*XROWS; pair += 14) {
        int ci = pair / XROWS;
        int r  = pair - ci*XROWS;
        int gr = 8*rt - 1 + r;
        __half* row = &sX[pair*XPITCH];
        if (gr < 0 || gr >= HIN) {
            if (lane < 29) *(uint4*)&row[8*lane] = make_uint4(0,0,0,0);
        } else {
            const float4* xb = (const float4*)(x + ((size_t)(b*CIN + ci)*HIN + gr)*WIN);
            float4 a = xb[lane];
            *(__half2*)&row[2 + 4*lane]     = __floats2half2_rn(a.x, a.y);
            *(__half2*)&row[2 + 4*lane + 2] = __floats2half2_rn(a.z, a.w);
            if (lane < 24) {
                float4 c4 = xb[lane + 32];
                *(__half2*)&row[2 + 4*(lane+32)]     = __floats2half2_rn(c4.x, c4.y);
                *(__half2*)&row[2 + 4*(lane+32) + 2] = __floats2half2_rn(c4.z, c4.w);
            } else if (lane == 24) {
                *(__half2*)&row[0] = __floats2half2_rn(0.f, 0.f);
            }
        }
    }

    // ---- staging NaN halo cols (once) ----
    {
        const __half2 NH2 = __halves2half2(__ushort_as_half((unsigned short)0x7e00),
                                           __ushort_as_half((unsigned short)0x7e00));
        for (int i = tid; i < CO*8; i += CONV_THREADS) {
            int ch = i >> 3, j = i & 7;
            int col = (j < 2) ? 2*j : 116 + 2*(j - 2);
            *(__half2*)&sY[ch*SYP + col] = NH2;
        }
    }

    // ---- top halo row 0 in gmem (rt==0 blocks only) ----
    if (rt == 0) {
        uint4 nv;
        nv.x = nv.y = nv.z = nv.w = 0x7e007e00u;
        for (int i = tid; i < CO*16; i += CONV_THREADS) {
            int ch = i >> 4, cu = i & 15;
            *(uint4*)(g_yh + ((size_t)(b*CO + ch)*PROWS)*PP + cu*8) = nv;
        }
    }
    __syncthreads();

    const int mh = w & 1;
    const int ng = w >> 1;
    const int qr = lane >> 2;
    const int qc = lane & 3;

    const uint32_t a_base = (uint32_t)__cvta_generic_to_shared(A_s)
                          + (uint32_t)((lane & 15) * (APITCH*2))
                          + (uint32_t)((lane & 16) ? 16 : 0)
                          + (uint32_t)(mh ? 6*16*APITCH*2 : 0);

    const uint32_t sy_row = (tid < 192)
        ? (uint32_t)__cvta_generic_to_shared(&sY[tid*SYP]) : 0u;

    #pragma unroll 1
    for (int oyl = 0; oyl < RPB; ++oyl) {
        // ---- build B [112 n][40 k] ----
        {
            int ci = lane / 9;
            int rr = lane - ci*9;
            int ky = rr / 3;
            int kx = rr - ky*3;
            const __half* xs = &sX[(ci*XROWS + 2*oyl + ky)*XPITCH + kx + 1];
            #pragma unroll
            for (int j = 0; j < 8; ++j) {
                int n = w + 14*j;
                __half v = __float2half(0.f);
                if (lane < 27) v = xs[2*n];
                B_s[n*BPITCH + lane] = v;
            }
        }
        if (tid < 192)
            asm volatile("cp.async.bulk.wait_group 0;" ::: "memory");
        __syncthreads();

        // ---- MMA ----
        float acc[6][2][4];
        #pragma unroll
        for (int mi = 0; mi < 6; ++mi)
            #pragma unroll
            for (int ni = 0; ni < 2; ++ni)
                #pragma unroll
                for (int j = 0; j < 4; ++j) acc[mi][ni][j] = 0.f;

        #pragma unroll
        for (int ks = 0; ks < 2; ++ks) {
            const int kb = ks*16 + 2*qc;
            uint32_t bf[2][2];
            #pragma unroll
            for (int ni = 0; ni < 2; ++ni) {
                const __half* bp = &B_s[(ng*16 + ni*8 + qr)*BPITCH + kb];
                bf[ni][0] = *(const uint32_t*)(bp);
                bf[ni][1] = *(const uint32_t*)(bp + 8);
            }
            #pragma unroll
            for (int mi = 0; mi < 6; ++mi) {
                uint32_t a0, a1, a2, a3;
                ldsm_x4(a0, a1, a2, a3,
                        a_base + (uint32_t)(mi*16*APITCH*2 + ks*32));
                #pragma unroll
                for (int ni = 0; ni < 2; ++ni)
                    mma16816(acc[mi][ni][0], acc[mi][ni][1], acc[mi][ni][2], acc[mi][ni][3],
                             a0, a1, a2, a3, bf[ni][0], bf[ni][1]);
            }
        }

        // ---- bias, stats (smem slots), staging STS ----
        #pragma unroll
        for (int mi = 0; mi < 6; ++mi) {
            const int R0 = (mh*6 + mi)*16 + qr;
            const int R8 = R0 + 8;
            const float bias0 = sBias[R0];
            const float bias8 = sBias[R8];
            float s0 = 0.f, q0 = 0.f, s8 = 0.f, q8 = 0.f;
            #pragma unroll
            for (int ni = 0; ni < 2; ++ni) {
                const int C = ng*16 + ni*8 + 2*qc;
                float v0 = acc[mi][ni][0] + bias0;
                float v1 = acc[mi][ni][1] + bias0;
                float v2 = acc[mi][ni][2] + bias8;
                float v3 = acc[mi][ni][3] + bias8;
                *(__half2*)&sY[R0*SYP + 4 + C] = __floats2half2_rn(v0, v1);
                *(__half2*)&sY[R8*SYP + 4 + C] = __floats2half2_rn(v2, v3);
                s0 += v0 + v1;  q0 += v0*v0 + v1*v1;
                s8 += v2 + v3;  q8 += v2*v2 + v3*v3;
            }
            #pragma unroll
            for (int o = 1; o <= 2; o <<= 1) {
                s0 += __shfl_xor_sync(0xffffffffu, s0, o);
                q0 += __shfl_xor_sync(0xffffffffu, q0, o);
                s8 += __shfl_xor_sync(0xffffffffu, s8, o);
                q8 += __shfl_xor_sync(0xffffffffu, q8, o);
            }
            if (qc == 0) {
                sSumP[R0*7 + ng] += s0;
                sSqP [R0*7 + ng] += q0;
                sSumP[R8*7 + ng] += s8;
                sSqP [R8*7 + ng] += q8;
            }
        }
        __syncthreads();

        // ---- DMA copy-out ----
        if (tid < 192) {
            const int OY = 4*rt + oyl;
            asm volatile("fence.proxy.async.shared::cta;" ::: "memory");
            bulk_copy_s2g(g_yh + ((size_t)(b*CO + tid)*PROWS + OY + 1)*PP,
                          sy_row, 256);
            asm volatile("cp.async.bulk.commit_group;" ::: "memory");
        }
    }

    // ---- block-level stats reduce, then drain bulk copies ----
    if (tid < 192) {
        float s = 0.f, q = 0.f;
        #pragma unroll
        for (int j = 0; j < 7; ++j) { s += sSumP[tid*7 + j]; q += sSqP[tid*7 + j]; }
        atomicAdd(&g_sum[tid], s);
        atomicAdd(&g_sq [tid], q);
        asm volatile("cp.async.bulk.wait_group 0;" ::: "memory");
    }
}

// ---------------------------------------------------------------------------
// Computes per-channel scale/shift once, re-zeroes accumulators for the next
// graph replay.
__global__ void finalize_stats_kernel(const float* __restrict__ gamma,
                                      const float* __restrict__ beta) {
    int c = threadIdx.x;
    if (c >= CO) return;
    float invN  = 1.0f / (float)NPC;
    float mean  = g_sum[c] * invN;
    float var   = g_sq[c] * invN - mean*mean;
    float inv   = rsqrtf(var + 1e-5f);
    float scale = gamma[c] * inv;
    g_scale[c]  = scale;
    g_shift[c]  = beta[c] - mean*scale;
    g_sum[c] = 0.f;
    g_sq [c] = 0.f;
}

// ---------------------------------------------------------------------------
// BN + GELU + MaxPool (R13 measured-best body), direct from padded gmem.
#define POOL_THREADS 256
#define POOL_TOTAL  (B_*CO*(PH/2)*(PW/8))   // 1,204,224

__device__ __forceinline__ float gelu_win(__half wm, __half wM,
                                          float scale, float shift) {
    float a1 = fmaf(__half2float(wm), scale, shift);
    float a2 = fmaf(__half2float(wM), scale, shift);
    float lo = fminf(a1, a2);
    float hi = fmaxf(a1, a2);
    float r  = 0.5f*hi*(1.0f + erff(hi*0.70710678118654752f));
    if (hi < 0.f) {
        float gl = 0.5f*lo*(1.0f + erff(lo*0.70710678118654752f));
        r = fmaxf(r, gl);
    }
    return r;
}

__global__ __launch_bounds__(POOL_THREADS)
void bn_gelu_pool_kernel(float* __restrict__ out) {
    const int idx = blockIdx.x*POOL_THREADS + threadIdx.x;
    const int g   = idx % 7;             // col group: px = 8g
    const int t1  = idx / 7;
    const int u   = t1 % 28;             // row pair: py0 = 2u
    const int t2  = t1 / 28;             // b*CO + ch
    const int ch  = t2 % CO;
    const int px  = 8*g;
    const int py0 = 2*u;

    const float scale = g_scale[ch];
    const float shift = g_shift[ch];

    const __half* base = g_yh + (size_t)t2*(PROWS*PP) + (size_t)(4*u)*PP + 2*px;

    union U { uint4 v[3]; __half2 h[12]; };
    U r0, r1, r2;
    #pragma unroll
    for (int k = 0; k < 3; ++k) r0.v[k] = *(const uint4*)(base + 8*k);
    #pragma unroll
    for (int k = 0; k < 3; ++k) r1.v[k] = *(const uint4*)(base + PP + 8*k);
    #pragma unroll
    for (int k = 0; k < 3; ++k) r2.v[k] = *(const uint4*)(base + 2*PP + 8*k);

    __half2 vmin[12], vmax[12];
    #pragma unroll
    for (int j = 0; j < 12; ++j) {
        vmax[j] = __hmax2(__hmax2(r0.h[j], r1.h[j]), r2.h[j]);
        vmin[j] = __hmin2(__hmin2(r0.h[j], r1.h[j]), r2.h[j]);
    }

    float* op0 = &out[(size_t)(t2*PH + py0)*PW + px];

    {   // outputs for py0
        const __half* Hm = (const __half*)vmin;
        const __half* HM = (const __half*)vmax;
        float4 oA, oB;
        float* ovA = (float*)&oA;
        float* ovB = (float*)&oB;
        #pragma unroll
        for (int j = 0; j < 4; ++j) {
            ovA[j] = gelu_win(__hmin(Hm[2*j+3], __hmin(Hm[2*j+4], Hm[2*j+5])),
                              __hmax(HM[2*j+3], __hmax(HM[2*j+4], HM[2*j+5])),
                              scale, shift);
            ovB[j] = gelu_win(__hmin(Hm[2*j+11], __hmin(Hm[2*j+12], Hm[2*j+13])),
                              __hmax(HM[2*j+11], __hmax(HM[2*j+12], HM[2*j+13])),
                              scale, shift);
        }
        *(float4*)op0       = oA;
        *(float4*)(op0 + 4) = oB;
    }

    U r3, r4;
    #pragma unroll
    for (int k = 0; k < 3; ++k) r3.v[k] = *(const uint4*)(base + 3*PP + 8*k);
    #pragma unroll
    for (int k = 0; k < 3; ++k) r4.v[k] = *(const uint4*)(base + 4*PP + 8*k);

    #pragma unroll
    for (int j = 0; j < 12; ++j) {
        vmax[j] = __hmax2(__hmax2(r2.h[j], r3.h[j]), r4.h[j]);
        vmin[j] = __hmin2(__hmin2(r2.h[j], r3.h[j]), r4.h[j]);
    }

    {   // outputs for py0+1
        const __half* Hm = (const __half*)vmin;
        const __half* HM = (const __half*)vmax;
        float4 oA, oB;
        float* ovA = (float*)&oA;
        float* ovB = (float*)&oB;
        #pragma unroll
        for (int j = 0; j < 4; ++j) {
            ovA[j] = gelu_win(__hmin(Hm[2*j+3], __hmin(Hm[2*j+4], Hm[2*j+5])),
                              __hmax(HM[2*j+3], __hmax(HM[2*j+4], HM[2*j+5])),
                              scale, shift);
            ovB[j] = gelu_win(__hmin(Hm[2*j+11], __hmin(Hm[2*j+12], Hm[2*j+13])),
                              __hmax(HM[2*j+11], __hmax(HM[2*j+12], HM[2*j+13])),
                              scale, shift);
        }
        *(float4*)(op0 + PW)     = oA;
        *(float4*)(op0 + PW + 4) = oB;
    }
}

// ---------------------------------------------------------------------------
extern "C" void kernel_launch(void* const* d_in, const int* in_sizes, int n_in,
                              void* d_out, int out_size) {
    const float* x      = (const float*)d_in[0];
    const float* conv_w = (const float*)d_in[1];
    const float* conv_b = (const float*)d_in[2];
    const float* gamma  = (const float*)d_in[3];
    const float* beta   = (const float*)d_in[4];
    float* out = (float*)d_out;

    cudaFuncSetAttribute(conv_mma_kernel,
                         cudaFuncAttributeMaxDynamicSharedMemorySize, CONV_SMEM);

    wprep_kernel<<<(CO*32 + 255)/256, 256>>>(conv_w);
    conv_mma_kernel<<<dim3(28, B_), CONV_THREADS, CONV_SMEM>>>(x, conv_b);
    finalize_stats_kernel<<<1, CO>>>(gamma, beta);
    bn_gelu_pool_kernel<<<POOL_TOTAL/POOL_THREADS, POOL_THREADS>>>(out);
}

// round 17
// speedup vs baseline: 1.1278x; 1.0342x over previous
#include <cuda_runtime.h>
#include <cuda_fp16.h>
#include <math.h>
#include <stdint.h>

#define B_    32
#define CIN   3
#define HIN   224
#define WIN   224
#define CO    192
#define OH    112
#define OW    112
#define PH    56
#define PW    56
#define NPC   (B_*OH*OW)   // 401408

// padded y layout: per (b,c) plane = 113 rows x 128 halves.
#define PP     128
#define PROWS  113

// -------- device scratch ----------------------------------------------------
__device__ __half g_yh[(size_t)B_*CO*PROWS*PP];   // ~178 MB padded conv output
__device__ __half g_wh[CO*32];                    // fp16 weights, taps 27..31 = 0
__device__ float g_sig[32*40];                    // B^T B moments; finalize re-zeroes
__device__ float g_scale[CO];
__device__ float g_shift[CO];

// ---------------------------------------------------------------------------
__global__ void wprep_kernel(const float* __restrict__ conv_w) {
    int i = blockIdx.x*256 + threadIdx.x;
    if (i >= CO*32) return;
    int co = i >> 5, k = i & 31;
    float v = (k < 27) ? conv_w[co*27 + k] : 0.f;
    g_wh[i] = __float2half(v);
}

// ---------------------------------------------------------------------------
__device__ __forceinline__ void mma16816(float& d0, float& d1, float& d2, float& d3,
                                         uint32_t a0, uint32_t a1, uint32_t a2, uint32_t a3,
                                         uint32_t b0, uint32_t b1) {
    asm volatile(
        "mma.sync.aligned.m16n8k16.row.col.f32.f16.f16.f32 "
        "{%0,%1,%2,%3},{%4,%5,%6,%7},{%8,%9},{%0,%1,%2,%3};"
        : "+f"(d0), "+f"(d1), "+f"(d2), "+f"(d3)
        : "r"(a0), "r"(a1), "r"(a2), "r"(a3), "r"(b0), "r"(b1));
}

__device__ __forceinline__ void ldsm_x4(uint32_t& r0, uint32_t& r1,
                                        uint32_t& r2, uint32_t& r3, uint32_t p) {
    asm volatile("ldmatrix.sync.aligned.m8n8.x4.shared.b16 {%0,%1,%2,%3},[%4];"
                 : "=r"(r0), "=r"(r1), "=r"(r2), "=r"(r3) : "r"(p));
}

__device__ __forceinline__ void ldsm_x4_t(uint32_t& r0, uint32_t& r1,
                                          uint32_t& r2, uint32_t& r3, uint32_t p) {
    asm volatile("ldmatrix.sync.aligned.m8n8.x4.trans.shared.b16 {%0,%1,%2,%3},[%4];"
                 : "=r"(r0), "=r"(r1), "=r"(r2), "=r"(r3) : "r"(p));
}

__device__ __forceinline__ void ldsm_x2_t(uint32_t& r0, uint32_t& r1, uint32_t p) {
    asm volatile("ldmatrix.sync.aligned.m8n8.x2.trans.shared.b16 {%0,%1},[%2];"
                 : "=r"(r0), "=r"(r1) : "r"(p));
}

__device__ __forceinline__ void bulk_copy_s2g(void* gdst, uint32_t ssrc, int bytes) {
    asm volatile("cp.async.bulk.global.shared::cta.bulk_group [%0], [%1], %2;"
                 :: "l"(gdst), "r"(ssrc), "r"(bytes) : "memory");
}

// ---------------------------------------------------------------------------
// Implicit-GEMM conv, 4 output rows per block. Stats via Sigma = B^T B
// (ones-column trick at k=32 gives colsum). No per-element stat shuffles/RMW.
#define CONV_THREADS 448
#define RPB     4
#define XROWS   9
#define XPITCH  232
#define APITCH  40
#define BPITCH  40
#define SYP     136
#define A_OFF   0                            // 192*40  = 7680
#define X_OFF   (CO*APITCH)                  // 27*232  = 6264
#define B_OFF   (X_OFF + CIN*XROWS*XPITCH)   // 112*40  = 4480
#define Y_OFF   (B_OFF + OW*BPITCH)          // 192*136 = 26112
#define H_TOT   (Y_OFF + CO*SYP)             // 44536 halves
#define NF      (192 + 32*40)                // bias + Sigma = 1472 floats
#define CONV_SMEM (H_TOT*2 + NF*4)           // 89072 + 5888 = 94960 B

__global__ __launch_bounds__(CONV_THREADS, 2)
void conv_mma_kernel(const float* __restrict__ x,
                     const float* __restrict__ conv_b) {
    extern __shared__ __half sm[];
    __half* A_s = sm + A_OFF;
    __half* sX  = sm + X_OFF;
    __half* B_s = sm + B_OFF;
    __half* sY  = sm + Y_OFF;
    float*  sBias = (float*)(sm + H_TOT);
    float*  sSig  = sBias + 192;         // [32][40]

    const int tid  = threadIdx.x;
    const int lane = tid & 31;
    const int w    = tid >> 5;
    const int rt   = blockIdx.x;    // 4-row tile, 0..27
    const int b    = blockIdx.y;

    if (tid < 192) sBias[tid] = conv_b[tid];
    for (int i = tid; i < 32*40; i += CONV_THREADS) sSig[i] = 0.f;

    // ---- A: copy prebuilt fp16 weights ----
    {
        const uint32_t* src = (const uint32_t*)g_wh;
        uint32_t* dst = (uint32_t*)A_s;          // pitch 20 uints
        for (int i = tid; i < CO*16; i += CONV_THREADS) {
            int co = i >> 4, ku = i & 15;
            dst[co*20 + ku] = src[i];
        }
    }

    // ---- B_s cols 32..39 constant init: col 32 = 1 (ones column), 33..39 = 0
    for (int i = tid; i < OW*4; i += CONV_THREADS) {
        int n = i >> 2, j = i & 3;
        __half2 v = (j == 0) ? __halves2half2(__float2half(1.f), __float2half(0.f))
                             : __halves2half2(__float2half(0.f), __float2half(0.f));
        *(__half2*)&B_s[n*BPITCH + 32 + 2*j] = v;
    }

    // ---- stage 9 rows x 3 ci, coalesced ----
    for (int pair = w; pair < CIN*XROWS; pair += 14) {
        int ci = pair / XROWS;
        int r  = pair - ci*XROWS;
        int gr = 8*rt - 1 + r;
        __half* row = &sX[pair*XPITCH];
        if (gr < 0 || gr >= HIN) {
            if (lane < 29) *(uint4*)&row[8*lane] = make_uint4(0,0,0,0);
        } else {
            const float4* xb = (const float4*)(x + ((size_t)(b*CIN + ci)*HIN + gr)*WIN);
            float4 a = xb[lane];
            *(__half2*)&row[2 + 4*lane]     = __floats2half2_rn(a.x, a.y);
            *(__half2*)&row[2 + 4*lane + 2] = __floats2half2_rn(a.z, a.w);
            if (lane < 24) {
                float4 c4 = xb[lane + 32];
                *(__half2*)&row[2 + 4*(lane+32)]     = __floats2half2_rn(c4.x, c4.y);
                *(__half2*)&row[2 + 4*(lane+32) + 2] = __floats2half2_rn(c4.z, c4.w);
            } else if (lane == 24) {
                *(__half2*)&row[0] = __floats2half2_rn(0.f, 0.f);
            }
        }
    }

    // ---- staging NaN halo cols (once) ----
    {
        const __half2 NH2 = __halves2half2(__ushort_as_half((unsigned short)0x7e00),
                                           __ushort_as_half((unsigned short)0x7e00));
        for (int i = tid; i < CO*8; i += CONV_THREADS) {
            int ch = i >> 3, j = i & 7;
            int col = (j < 2) ? 2*j : 116 + 2*(j - 2);
            *(__half2*)&sY[ch*SYP + col] = NH2;
        }
    }

    // ---- top halo row 0 in gmem (rt==0 blocks only) ----
    if (rt == 0) {
        uint4 nv;
        nv.x = nv.y = nv.z = nv.w = 0x7e007e00u;
        for (int i = tid; i < CO*16; i += CONV_THREADS) {
            int ch = i >> 4, cu = i & 15;
            *(uint4*)(g_yh + ((size_t)(b*CO + ch)*PROWS)*PP + cu*8) = nv;
        }
    }
    __syncthreads();

    const int mh = w & 1;
    const int ng = w >> 1;
    const int qr = lane >> 2;
    const int qc = lane & 3;

    const uint32_t a_base = (uint32_t)__cvta_generic_to_shared(A_s)
                          + (uint32_t)((lane & 15) * (APITCH*2))
                          + (uint32_t)((lane & 16) ? 16 : 0)
                          + (uint32_t)(mh ? 6*16*APITCH*2 : 0);

    const uint32_t sy_row = (tid < 192)
        ? (uint32_t)__cvta_generic_to_shared(&sY[tid*SYP]) : 0u;

    // Sigma-GEMM lane pointers (warps 0..9): smi = m-tile (kA 16*smi), sni = n-tile (kB 8*sni)
    const int smi = (w < 5) ? 0 : 1;
    const int sni = (w < 5) ? w : w - 5;
    const uint32_t bs_base = (uint32_t)__cvta_generic_to_shared(B_s);
    const int gA = lane >> 3;
    const uint32_t sig_a0 = bs_base
        + (uint32_t)(((8*(gA>>1) + (lane & 7))*BPITCH + 16*smi + 8*(gA & 1)) * 2);
    const uint32_t sig_b0 = bs_base
        + (uint32_t)(((8*((lane>>3) & 1) + (lane & 7))*BPITCH + 8*sni) * 2);

    #pragma unroll 1
    for (int oyl = 0; oyl < RPB; ++oyl) {
        // ---- build B [112 n][k: 0..31 from taps; 32=ones kept] ----
        {
            int ci = lane / 9;
            int rr = lane - ci*9;
            int ky = rr / 3;
            int kx = rr - ky*3;
            const __half* xs = &sX[(ci*XROWS + 2*oyl + ky)*XPITCH + kx + 1];
            #pragma unroll
            for (int j = 0; j < 8; ++j) {
                int n = w + 14*j;
                __half v = __float2half(0.f);
                if (lane < 27) v = xs[2*n];
                B_s[n*BPITCH + lane] = v;
            }
        }
        if (tid < 192)
            asm volatile("cp.async.bulk.wait_group 0;" ::: "memory");
        __syncthreads();

        // ---- main MMA ----
        float acc[6][2][4];
        #pragma unroll
        for (int mi = 0; mi < 6; ++mi)
            #pragma unroll
            for (int ni = 0; ni < 2; ++ni)
                #pragma unroll
                for (int j = 0; j < 4; ++j) acc[mi][ni][j] = 0.f;

        #pragma unroll
        for (int ks = 0; ks < 2; ++ks) {
            const int kb = ks*16 + 2*qc;
            uint32_t bf[2][2];
            #pragma unroll
            for (int ni = 0; ni < 2; ++ni) {
                const __half* bp = &B_s[(ng*16 + ni*8 + qr)*BPITCH + kb];
                bf[ni][0] = *(const uint32_t*)(bp);
                bf[ni][1] = *(const uint32_t*)(bp + 8);
            }
            #pragma unroll
            for (int mi = 0; mi < 6; ++mi) {
                uint32_t a0, a1, a2, a3;
                ldsm_x4(a0, a1, a2, a3,
                        a_base + (uint32_t)(mi*16*APITCH*2 + ks*32));
                #pragma unroll
                for (int ni = 0; ni < 2; ++ni)
                    mma16816(acc[mi][ni][0], acc[mi][ni][1], acc[mi][ni][2], acc[mi][ni][3],
                             a0, a1, a2, a3, bf[ni][0], bf[ni][1]);
            }
        }

        // ---- epilogue: bias + staging STS only (stats gone) ----
        #pragma unroll
        for (int mi = 0; mi < 6; ++mi) {
            const int R0 = (mh*6 + mi)*16 + qr;
            const int R8 = R0 + 8;
            const float bias0 = sBias[R0];
            const float bias8 = sBias[R8];
            #pragma unroll
            for (int ni = 0; ni < 2; ++ni) {
                const int C = ng*16 + ni*8 + 2*qc;
                *(__half2*)&sY[R0*SYP + 4 + C] =
                    __floats2half2_rn(acc[mi][ni][0] + bias0, acc[mi][ni][1] + bias0);
                *(__half2*)&sY[R8*SYP + 4 + C] =
                    __floats2half2_rn(acc[mi][ni][2] + bias8, acc[mi][ni][3] + bias8);
            }
        }

        // ---- Sigma-GEMM: warps 0..9 accumulate B^T B tiles into sSig ----
        if (w < 10) {
            float sd0 = 0.f, sd1 = 0.f, sd2 = 0.f, sd3 = 0.f;
            #pragma unroll
            for (int ks2 = 0; ks2 < 7; ++ks2) {
                uint32_t a0, a1, a2, a3, b0, b1;
                ldsm_x4_t(a0, a1, a2, a3, sig_a0 + (uint32_t)(ks2*16*BPITCH*2));
                ldsm_x2_t(b0, b1,         sig_b0 + (uint32_t)(ks2*16*BPITCH*2));
                mma16816(sd0, sd1, sd2, sd3, a0, a1, a2, a3, b0, b1);
            }
            const int r0 = 16*smi + qr;
            const int cc = 8*sni + 2*qc;
            sSig[r0*40 + cc]         += sd0;
            sSig[r0*40 + cc + 1]     += sd1;
            sSig[(r0+8)*40 + cc]     += sd2;
            sSig[(r0+8)*40 + cc + 1] += sd3;
        }
        __syncthreads();

        // ---- DMA copy-out ----
        if (tid < 192) {
            const int OY = 4*rt + oyl;
            asm volatile("fence.proxy.async.shared::cta;" ::: "memory");
            bulk_copy_s2g(g_yh + ((size_t)(b*CO + tid)*PROWS + OY + 1)*PP,
                          sy_row, 256);
            asm volatile("cp.async.bulk.commit_group;" ::: "memory");
        }
    }

    // ---- block-level Sigma reduce to global ----
    for (int i = tid; i < 32*40; i += CONV_THREADS)
        atomicAdd(&g_sig[i], sSig[i]);
    if (tid < 192)
        asm volatile("cp.async.bulk.wait_group 0;" ::: "memory");
}

// ---------------------------------------------------------------------------
// Analytic BN stats from Sigma; re-zeroes g_sig for the next graph replay.
__global__ void finalize_stats_kernel(const float* __restrict__ gamma,
                                      const float* __restrict__ beta,
                                      const float* __restrict__ conv_b) {
    __shared__ float sSig[32*40];
    const int t = threadIdx.x;   // 192
    for (int i = t; i < 32*40; i += 192) { sSig[i] = g_sig[i]; g_sig[i] = 0.f; }
    __syncthreads();
    if (t >= CO) return;
    float wreg[27];
    #pragma unroll
    for (int k = 0; k < 27; ++k) wreg[k] = __half2float(g_wh[t*32 + k]);
    const float bb = conv_b[t];
    float dot = 0.f, ss = 0.f;
    for (int k = 0; k < 27; ++k) {
        dot += wreg[k] * sSig[k*40 + 32];          // colsum via ones column
        float a = 0.f;
        for (int k2 = 0; k2 < 27; ++k2) a += wreg[k2] * sSig[k*40 + k2];
        ss += wreg[k] * a;
    }
    const float N   = (float)NPC;
    const float s   = dot + N*bb;
    const float q   = ss + 2.f*bb*dot + N*bb*bb;
    const float mean = s / N;
    const float var  = q / N - mean*mean;
    const float inv  = rsqrtf(var + 1e-5f);
    const float scale = gamma[t] * inv;
    g_scale[t] = scale;
    g_shift[t] = beta[t] - mean*scale;
}

// ---------------------------------------------------------------------------
// BN + GELU + MaxPool (R13 measured-best body), direct from padded gmem.
#define POOL_THREADS 256
#define POOL_TOTAL  (B_*CO*(PH/2)*(PW/8))   // 1,204,224

__device__ __forceinline__ float gelu_win(__half wm, __half wM,
                                          float scale, float shift) {
    float a1 = fmaf(__half2float(wm), scale, shift);
    float a2 = fmaf(__half2float(wM), scale, shift);
    float lo = fminf(a1, a2);
    float hi = fmaxf(a1, a2);
    float r  = 0.5f*hi*(1.0f + erff(hi*0.70710678118654752f));
    if (hi < 0.f) {
        float gl = 0.5f*lo*(1.0f + erff(lo*0.70710678118654752f));
        r = fmaxf(r, gl);
    }
    return r;
}

__global__ __launch_bounds__(POOL_THREADS)
void bn_gelu_pool_kernel(float* __restrict__ out) {
    const int idx = blockIdx.x*POOL_THREADS + threadIdx.x;
    const int g   = idx % 7;
    const int t1  = idx / 7;
    const int u   = t1 % 28;
    const int t2  = t1 / 28;             // b*CO + ch
    const int ch  = t2 % CO;
    const int px  = 8*g;
    const int py0 = 2*u;

    const float scale = g_scale[ch];
    const float shift = g_shift[ch];

    const __half* base = g_yh + (size_t)t2*(PROWS*PP) + (size_t)(4*u)*PP + 2*px;

    union U { uint4 v[3]; __half2 h[12]; };
    U r0, r1, r2;
    #pragma unroll
    for (int k = 0; k < 3; ++k) r0.v[k] = *(const uint4*)(base + 8*k);
    #pragma unroll
    for (int k = 0; k < 3; ++k) r1.v[k] = *(const uint4*)(base + PP + 8*k);
    #pragma unroll
    for (int k = 0; k < 3; ++k) r2.v[k] = *(const uint4*)(base + 2*PP + 8*k);

    __half2 vmin[12], vmax[12];
    #pragma unroll
    for (int j = 0; j < 12; ++j) {
        vmax[j] = __hmax2(__hmax2(r0.h[j], r1.h[j]), r2.h[j]);
        vmin[j] = __hmin2(__hmin2(r0.h[j], r1.h[j]), r2.h[j]);
    }

    float* op0 = &out[(size_t)(t2*PH + py0)*PW + px];

    {
        const __half* Hm = (const __half*)vmin;
        const __half* HM = (const __half*)vmax;
        float4 oA, oB;
        float* ovA = (float*)&oA;
        float* ovB = (float*)&oB;
        #pragma unroll
        for (int j = 0; j < 4; ++j) {
            ovA[j] = gelu_win(__hmin(Hm[2*j+3], __hmin(Hm[2*j+4], Hm[2*j+5])),
                              __hmax(HM[2*j+3], __hmax(HM[2*j+4], HM[2*j+5])),
                              scale, shift);
            ovB[j] = gelu_win(__hmin(Hm[2*j+11], __hmin(Hm[2*j+12], Hm[2*j+13])),
                              __hmax(HM[2*j+11], __hmax(HM[2*j+12], HM[2*j+13])),
                              scale, shift);
        }
        *(float4*)op0       = oA;
        *(float4*)(op0 + 4) = oB;
    }

    U r3, r4;
    #pragma unroll
    for (int k = 0; k < 3; ++k) r3.v[k] = *(const uint4*)(base + 3*PP + 8*k);
    #pragma unroll
    for (int k = 0; k < 3; ++k) r4.v[k] = *(const uint4*)(base + 4*PP + 8*k);

    #pragma unroll
    for (int j = 0; j < 12; ++j) {
        vmax[j] = __hmax2(__hmax2(r2.h[j], r3.h[j]), r4.h[j]);
        vmin[j] = __hmin2(__hmin2(r2.h[j], r3.h[j]), r4.h[j]);
    }

    {
        const __half* Hm = (const __half*)vmin;
        const __half* HM = (const __half*)vmax;
        float4 oA, oB;
        float* ovA = (float*)&oA;
        float* ovB = (float*)&oB;
        #pragma unroll
        for (int j = 0; j < 4; ++j) {
            ovA[j] = gelu_win(__hmin(Hm[2*j+3], __hmin(Hm[2*j+4], Hm[2*j+5])),
                              __hmax(HM[2*j+3], __hmax(HM[2*j+4], HM[2*j+5])),
                              scale, shift);
            ovB[j] = gelu_win(__hmin(Hm[2*j+11], __hmin(Hm[2*j+12], Hm[2*j+13])),
                              __hmax(HM[2*j+11], __hmax(HM[2*j+12], HM[2*j+13])),
                              scale, shift);
        }
        *(float4*)(op0 + PW)     = oA;
        *(float4*)(op0 + PW + 4) = oB;
    }
}

// ---------------------------------------------------------------------------
extern "C" void kernel_launch(void* const* d_in, const int* in_sizes, int n_in,
                              void* d_out, int out_size) {
    const float* x      = (const float*)d_in[0];
    const float* conv_w = (const float*)d_in[1];
    const float* conv_b = (const float*)d_in[2];
    const float* gamma  = (const float*)d_in[3];
    const float* beta   = (const float*)d_in[4];
    float* out = (float*)d_out;

    cudaFuncSetAttribute(conv_mma_kernel,
                         cudaFuncAttributeMaxDynamicSharedMemorySize, CONV_SMEM);

    wprep_kernel<<<(CO*32 + 255)/256, 256>>>(conv_w);
    conv_mma_kernel<<<dim3(28, B_), CONV_THREADS, CONV_SMEM>>>(x, conv_b);
    finalize_stats_kernel<<<1, CO>>>(gamma, beta, conv_b);
    bn_gelu_pool_kernel<<<POOL_TOTAL/POOL_THREADS, POOL_THREADS>>>(out);
}